// round 16
// baseline (speedup 1.0000x reference)
#include <cuda_runtime.h>
#include <cuda_bf16.h>
#include <cstdint>

// Problem constants
#define BATCH 2
#define SEQ   2048
#define HID   1024
#define NH    16
#define HD    64
#define MROWS (BATCH * SEQ)   // 4096

// ---------------- scratch (device globals; no allocation allowed) -------
__device__ float g_h[MROWS * HID];
__device__ float g_q[MROWS * HID];
__device__ float g_k[MROWS * HID];
__device__ float g_v[MROWS * HID];
__device__ float g_ctx[MROWS * HID];

// ---------------- helpers -----------------------------------------------
__device__ __forceinline__ uint32_t smem_u32(const void* p) {
    uint32_t a;
    asm("{ .reg .u64 t; cvta.to.shared.u64 t, %1; cvt.u32.u64 %0, t; }"
        : "=r"(a) : "l"(p));
    return a;
}
#define CP_ASYNC16(dst, src) \
    asm volatile("cp.async.cg.shared.global [%0], [%1], 16;" \
                 :: "r"(dst), "l"(src) : "memory")
#define CP_COMMIT() asm volatile("cp.async.commit_group;" ::: "memory")
#define CP_WAIT0()  asm volatile("cp.async.wait_group 0;" ::: "memory")

// ---------------- LayerNorm --------------------------------------------
__global__ void __launch_bounds__(256) ln_kernel(const float* __restrict__ X,
                                                 const float* __restrict__ gamma,
                                                 const float* __restrict__ beta,
                                                 float* __restrict__ Y) {
    int row = blockIdx.x;
    const float4* xr = (const float4*)(X + (size_t)row * HID);
    float4 v = xr[threadIdx.x];
    float s  = v.x + v.y + v.z + v.w;
    float ss = v.x*v.x + v.y*v.y + v.z*v.z + v.w*v.w;

    #pragma unroll
    for (int off = 16; off; off >>= 1) {
        s  += __shfl_xor_sync(0xffffffffu, s,  off);
        ss += __shfl_xor_sync(0xffffffffu, ss, off);
    }
    __shared__ float rs[8], rss[8];
    int w = threadIdx.x >> 5, ln = threadIdx.x & 31;
    if (ln == 0) { rs[w] = s; rss[w] = ss; }
    __syncthreads();
    float ts = 0.f, tss = 0.f;
    #pragma unroll
    for (int i = 0; i < 8; i++) { ts += rs[i]; tss += rss[i]; }
    float mu  = ts * (1.0f / HID);
    float var = tss * (1.0f / HID) - mu * mu;
    float inv = rsqrtf(var + 1e-12f);

    float4 g  = ((const float4*)gamma)[threadIdx.x];
    float4 be = ((const float4*)beta)[threadIdx.x];
    float4 r;
    r.x = (v.x - mu) * inv * g.x + be.x;
    r.y = (v.y - mu) * inv * g.y + be.y;
    r.z = (v.z - mu) * inv * g.z + be.z;
    r.w = (v.w - mu) * inv * g.w + be.w;
    ((float4*)(Y + (size_t)row * HID))[threadIdx.x] = r;
}

// ========== SGEMM core (R10-proven, BKG=16, double-buffered) ============
// C[m][n] = sum_k A[m][k]*B[n][k] + bias[n]
#define BM 128
#define BN 128
#define BKG 16
#define SPAD 132
#define TILE_F (BKG * SPAD)   // 2112 floats per operand tile

__device__ __forceinline__ void gemm_core(const float* __restrict__ A,
                                          const float* __restrict__ B,
                                          const float* __restrict__ bias,
                                          float* __restrict__ C,
                                          int M, int N, int K,
                                          float* sm, int m0, int n0) {
    int tid = threadIdx.x;
    int tx = tid & 15, ty = tid >> 4;

    const float* Ab = A + (size_t)m0 * K;
    const float* Bb = B + (size_t)n0 * K;

    float c[8][8];
    #pragma unroll
    for (int i = 0; i < 8; i++)
        #pragma unroll
        for (int j = 0; j < 8; j++) c[i][j] = 0.f;

    float4 ra[2], rb[2];
    #define G_LDG(k0) do { \
        _Pragma("unroll") \
        for (int i = 0; i < 2; i++) { \
            int id = tid + (i << 8); \
            int row = id >> 2, kq = (id & 3) << 2; \
            ra[i] = *(const float4*)&Ab[(size_t)row * K + (k0) + kq]; \
            rb[i] = *(const float4*)&Bb[(size_t)row * K + (k0) + kq]; \
        } } while (0)
    #define G_STS(buf) do { \
        float* As_ = sm + (buf) * 2 * TILE_F; \
        float* Bs_ = As_ + TILE_F; \
        _Pragma("unroll") \
        for (int i = 0; i < 2; i++) { \
            int id = tid + (i << 8); \
            int row = id >> 2, kq = (id & 3) << 2; \
            As_[(kq + 0) * SPAD + row] = ra[i].x; \
            As_[(kq + 1) * SPAD + row] = ra[i].y; \
            As_[(kq + 2) * SPAD + row] = ra[i].z; \
            As_[(kq + 3) * SPAD + row] = ra[i].w; \
            Bs_[(kq + 0) * SPAD + row] = rb[i].x; \
            Bs_[(kq + 1) * SPAD + row] = rb[i].y; \
            Bs_[(kq + 2) * SPAD + row] = rb[i].z; \
            Bs_[(kq + 3) * SPAD + row] = rb[i].w; \
        } } while (0)

    G_LDG(0);
    G_STS(0);
    __syncthreads();

    const int nst = K / BKG;
    for (int it = 0; it < nst; it++) {
        int buf = it & 1;
        bool more = (it + 1) < nst;
        if (more) G_LDG((it + 1) * BKG);

        const float* As = sm + buf * 2 * TILE_F;
        const float* Bs = As + TILE_F;
        #pragma unroll
        for (int k = 0; k < BKG; k++) {
            float4 a0 = *(const float4*)&As[k * SPAD + ty * 8];
            float4 a1 = *(const float4*)&As[k * SPAD + ty * 8 + 4];
            // b-frag split: 16B lane stride -> conflict-free LDS.128
            float4 b0 = *(const float4*)&Bs[k * SPAD + tx * 4];
            float4 b1 = *(const float4*)&Bs[k * SPAD + tx * 4 + 64];
            #define G_ROW(i, av) \
                c[i][0] += (av) * b0.x; c[i][1] += (av) * b0.y; \
                c[i][2] += (av) * b0.z; c[i][3] += (av) * b0.w; \
                c[i][4] += (av) * b1.x; c[i][5] += (av) * b1.y; \
                c[i][6] += (av) * b1.z; c[i][7] += (av) * b1.w;
            G_ROW(0, a0.x) G_ROW(1, a0.y) G_ROW(2, a0.z) G_ROW(3, a0.w)
            G_ROW(4, a1.x) G_ROW(5, a1.y) G_ROW(6, a1.z) G_ROW(7, a1.w)
            #undef G_ROW
        }
        if (more) {
            G_STS(buf ^ 1);
            __syncthreads();
        }
    }

    // epilogue: cols n0 + tx*4 (j 0-3) and n0 + 64 + tx*4 (j 4-7)
    float4 bi0 = *(const float4*)&bias[n0 + tx * 4];
    float4 bi1 = *(const float4*)&bias[n0 + 64 + tx * 4];
    #pragma unroll
    for (int i = 0; i < 8; i++) {
        int row = m0 + ty * 8 + i;
        float4 r0, r1;
        r0.x = c[i][0] + bi0.x; r0.y = c[i][1] + bi0.y;
        r0.z = c[i][2] + bi0.z; r0.w = c[i][3] + bi0.w;
        r1.x = c[i][4] + bi1.x; r1.y = c[i][5] + bi1.y;
        r1.z = c[i][6] + bi1.z; r1.w = c[i][7] + bi1.w;
        *(float4*)&C[(size_t)row * N + n0 + tx * 4]      = r0;
        *(float4*)&C[(size_t)row * N + n0 + 64 + tx * 4] = r1;
    }
    #undef G_LDG
    #undef G_STS
}

// Fused QKV: blockIdx.z selects (W, bias, C)
__global__ void __launch_bounds__(256, 2) sgemm_qkv(const float* __restrict__ A,
                                                    const float* __restrict__ W0,
                                                    const float* __restrict__ W1,
                                                    const float* __restrict__ W2,
                                                    const float* __restrict__ b0,
                                                    const float* __restrict__ b1,
                                                    const float* __restrict__ b2,
                                                    float* __restrict__ C0,
                                                    float* __restrict__ C1,
                                                    float* __restrict__ C2,
                                                    int M, int N, int K) {
    __shared__ float sm[4 * TILE_F];
    int z = blockIdx.z;
    const float* B    = (z == 0) ? W0 : (z == 1) ? W1 : W2;
    const float* bias = (z == 0) ? b0 : (z == 1) ? b1 : b2;
    float* C          = (z == 0) ? C0 : (z == 1) ? C1 : C2;
    gemm_core(A, B, bias, C, M, N, K, sm,
              blockIdx.y * BM, blockIdx.x * BN);
}

// Single GEMM (output projection)
__global__ void __launch_bounds__(256, 2) sgemm_one(const float* __restrict__ A,
                                                    const float* __restrict__ B,
                                                    const float* __restrict__ bias,
                                                    float* __restrict__ C,
                                                    int M, int N, int K) {
    __shared__ float sm[4 * TILE_F];
    gemm_core(A, B, bias, C, M, N, K, sm,
              blockIdx.y * BM, blockIdx.x * BN);
}

// ------- Flash attention: reg-transposed K store + deferred l-reduce ----
// Max-free softmax (scores bounded; mask exp underflows to 0 cleanly).
#define QT 128
#define KT 64
#define QSTR 132
#define KSTR 68
#define PSTR 68    // floats per q-row of P (64 k + 4 pad); 17 float4s
// floats: Q 64*132 + K 64*68 + V 64*68 + P 128*68 + msk 64 = 25920 (103.7 KB)
#define ATTN_SMEM_FLOATS (HD * QSTR + 2 * KT * KSTR + QT * PSTR + KT)
#define ATTN_SMEM_BYTES (ATTN_SMEM_FLOATS * 4)

__global__ void __launch_bounds__(256, 2) attn_kernel(const float* __restrict__ Q,
                                                      const float* __restrict__ K,
                                                      const float* __restrict__ V,
                                                      const float* __restrict__ amask,
                                                      float* __restrict__ O) {
    extern __shared__ float sm[];
    float* Qst = sm;                      // [HD][QSTR]  (d-major)
    float* Ksm = Qst + HD * QSTR;         // [HD][KSTR]  (d-major)
    float* Vsm = Ksm + KT * KSTR;         // [KT][KSTR]  (s-major)
    float* Psm = Vsm + KT * KSTR;         // [QT][PSTR]  (q-major)
    float* msk = Psm + QT * PSTR;         // [KT]
    float4* P4 = (float4*)Psm;            // stride 17 float4 per q-row
    const float4* V4 = (const float4*)Vsm;  // stride 17 float4 per s-row
    uint32_t su = smem_u32(sm);
    const uint32_t v_off = (uint32_t)((HD * QSTR + KT * KSTR) * 4);

    int b = blockIdx.z, hh = blockIdx.y;
    int q0 = blockIdx.x * QT;
    int tid = threadIdx.x;
    int tx = tid & 15, ty = tid >> 4;
    int sld = tid >> 4;        // load-group id (0..15)
    int d4  = (tid & 15) * 4;  // d-quad for loading

    size_t rowbase = ((size_t)b * SEQ) * HID + hh * HD;

    float4 kreg[4];   // kreg[j] = K[kk + 4*sld + j][d4..d4+3]
    float mreg = 1.0f;
    #define K_LDG(kk) do { \
        _Pragma("unroll") \
        for (int j = 0; j < 4; j++) { \
            int s = 4 * sld + j; \
            kreg[j] = *(const float4*)&K[rowbase + (size_t)((kk) + s) * HID + d4]; \
        } \
        if (tid < KT) mreg = amask[b * SEQ + (kk) + tid]; \
        } while (0)
    // In-register 4x4 transpose -> 4 STS.128 (s-consecutive per d).
    // Ksm[(d4+c)*KSTR + 4*sld + e] = K[kk+4*sld+e][d4+c]  (matches QK reads)
    #define K_STS() do { \
        int sb = 4 * sld; \
        float4 t; \
        t.x = kreg[0].x; t.y = kreg[1].x; t.z = kreg[2].x; t.w = kreg[3].x; \
        *(float4*)&Ksm[(d4 + 0) * KSTR + sb] = t; \
        t.x = kreg[0].y; t.y = kreg[1].y; t.z = kreg[2].y; t.w = kreg[3].y; \
        *(float4*)&Ksm[(d4 + 1) * KSTR + sb] = t; \
        t.x = kreg[0].z; t.y = kreg[1].z; t.z = kreg[2].z; t.w = kreg[3].z; \
        *(float4*)&Ksm[(d4 + 2) * KSTR + sb] = t; \
        t.x = kreg[0].w; t.y = kreg[1].w; t.z = kreg[2].w; t.w = kreg[3].w; \
        *(float4*)&Ksm[(d4 + 3) * KSTR + sb] = t; \
        if (tid < KT) msk[tid] = -1000.0f * (1.0f - mreg); \
        } while (0)
    #define V_CPA(kk) do { \
        _Pragma("unroll") \
        for (int j = 0; j < 4; j++) { \
            int s = sld + j * 16; \
            uint32_t dst = su + v_off + (uint32_t)(s * KSTR + d4) * 4; \
            CP_ASYNC16(dst, &V[rowbase + (size_t)((kk) + s) * HID + d4]); \
        } } while (0)

    // prologue: V(0) async, Q tile (transposed), K(0)+mask via regs
    V_CPA(0);
    CP_COMMIT();
    for (int idx = tid; idx < QT * HD; idx += 256) {
        int s = idx >> 6, d = idx & 63;
        Qst[d * QSTR + s] = Q[rowbase + (size_t)(q0 + s) * HID + d];
    }
    K_LDG(0);
    K_STS();
    CP_WAIT0();
    __syncthreads();   // Q, K(0), msk(0), V(0) all visible

    float l_i[8], o[8][4];
    #pragma unroll
    for (int i = 0; i < 8; i++) {
        l_i[i] = 0.f;
        #pragma unroll
        for (int dd = 0; dd < 4; dd++) o[i][dd] = 0.f;
    }

    for (int kk = 0; kk < SEQ; kk += KT) {
        bool more = (kk + KT) < SEQ;
        if (more) K_LDG(kk + KT);   // lands during QK/softmax

        // S = Q K^T   (reads Qst, Ksm)
        float sreg[8][4];
        #pragma unroll
        for (int i = 0; i < 8; i++)
            #pragma unroll
            for (int j = 0; j < 4; j++) sreg[i][j] = 0.f;

        #pragma unroll 4
        for (int d = 0; d < HD; d++) {
            float4 a0 = *(float4*)&Qst[d * QSTR + ty * 8];
            float4 a1 = *(float4*)&Qst[d * QSTR + ty * 8 + 4];
            float4 bq = *(float4*)&Ksm[d * KSTR + tx * 4];
            #define A_SR(i, av) \
                sreg[i][0] += (av) * bq.x; sreg[i][1] += (av) * bq.y; \
                sreg[i][2] += (av) * bq.z; sreg[i][3] += (av) * bq.w;
            A_SR(0, a0.x) A_SR(1, a0.y) A_SR(2, a0.z) A_SR(3, a0.w)
            A_SR(4, a1.x) A_SR(5, a1.y) A_SR(6, a1.z) A_SR(7, a1.w)
            #undef A_SR
        }
        float mk[4];
        #pragma unroll
        for (int j = 0; j < 4; j++) mk[j] = msk[tx * 4 + j];

        // max-free softmax: p = exp(s/8 + mask); per-lane partial l; write P
        #pragma unroll
        for (int i = 0; i < 8; i++) {
            float p0 = __expf(sreg[i][0] * 0.125f + mk[0]);
            float p1 = __expf(sreg[i][1] * 0.125f + mk[1]);
            float p2 = __expf(sreg[i][2] * 0.125f + mk[2]);
            float p3 = __expf(sreg[i][3] * 0.125f + mk[3]);
            l_i[i] += (p0 + p1) + (p2 + p3);   // lane-local partial (reduced once at end)
            float4 pv;
            pv.x = p0; pv.y = p1; pv.z = p2; pv.w = p3;
            P4[(ty * 8 + i) * 17 + tx] = pv;   // row q, col-quad tx (k=4tx..4tx+3)
        }
        CP_WAIT0();        // V(kk) landed (issuing thread)
        __syncthreads();   // (A) P + V(kk) visible; K(kk)/msk readers done

        if (more) K_STS();   // store K(kk+1)+msk — K readers finished at (A)

        // O += P @ V : kr blocked by 4; per-accumulator kr order = 0..63 asc
        #pragma unroll 4
        for (int kr4 = 0; kr4 < KT / 4; kr4++) {
            float4 vv0 = V4[(4 * kr4 + 0) * 17 + tx];
            float4 vv1 = V4[(4 * kr4 + 1) * 17 + tx];
            float4 vv2 = V4[(4 * kr4 + 2) * 17 + tx];
            float4 vv3 = V4[(4 * kr4 + 3) * 17 + tx];
            #pragma unroll
            for (int ih = 0; ih < 8; ih += 4) {
                float4 pq0 = P4[(ty * 8 + ih + 0) * 17 + kr4];
                float4 pq1 = P4[(ty * 8 + ih + 1) * 17 + kr4];
                float4 pq2 = P4[(ty * 8 + ih + 2) * 17 + kr4];
                float4 pq3 = P4[(ty * 8 + ih + 3) * 17 + kr4];
                #define A_OV4(i, pq) \
                    o[i][0] += pq.x * vv0.x; o[i][1] += pq.x * vv0.y; \
                    o[i][2] += pq.x * vv0.z; o[i][3] += pq.x * vv0.w; \
                    o[i][0] += pq.y * vv1.x; o[i][1] += pq.y * vv1.y; \
                    o[i][2] += pq.y * vv1.z; o[i][3] += pq.y * vv1.w; \
                    o[i][0] += pq.z * vv2.x; o[i][1] += pq.z * vv2.y; \
                    o[i][2] += pq.z * vv2.z; o[i][3] += pq.z * vv2.w; \
                    o[i][0] += pq.w * vv3.x; o[i][1] += pq.w * vv3.y; \
                    o[i][2] += pq.w * vv3.z; o[i][3] += pq.w * vv3.w;
                A_OV4(ih + 0, pq0)
                A_OV4(ih + 1, pq1)
                A_OV4(ih + 2, pq2)
                A_OV4(ih + 3, pq3)
                #undef A_OV4
            }
        }
        __syncthreads();   // (B) PV done: V free, P free, K(kk+1) visible
        if (more) {
            V_CPA(kk + KT);
            CP_COMMIT();
        }
    }

    // epilogue: one cross-lane l reduction (16-lane halves share a q-row set)
    #pragma unroll
    for (int i = 0; i < 8; i++) {
        float lt = l_i[i];
        #pragma unroll
        for (int off = 8; off; off >>= 1)
            lt += __shfl_xor_sync(0xffffffffu, lt, off);
        float inv = 1.0f / lt;
        int s = q0 + ty * 8 + i;
        float4 r;
        r.x = o[i][0] * inv; r.y = o[i][1] * inv;
        r.z = o[i][2] * inv; r.w = o[i][3] * inv;
        *(float4*)&O[rowbase + (size_t)s * HID + tx * 4] = r;
    }
    #undef K_LDG
    #undef K_STS
    #undef V_CPA
}

// ---------------- launch -------------------------------------------------
extern "C" void kernel_launch(void* const* d_in, const int* in_sizes, int n_in,
                              void* d_out, int out_size) {
    const float* hs    = (const float*)d_in[0];
    const float* amask = (const float*)d_in[1];
    const float* Wq    = (const float*)d_in[2];
    const float* bq    = (const float*)d_in[3];
    const float* Wk    = (const float*)d_in[4];
    const float* bk    = (const float*)d_in[5];
    const float* Wv    = (const float*)d_in[6];
    const float* bv    = (const float*)d_in[7];
    const float* Wd    = (const float*)d_in[8];
    const float* bd    = (const float*)d_in[9];
    const float* gamma = (const float*)d_in[10];
    const float* beta  = (const float*)d_in[11];
    float* out = (float*)d_out;

    float *h, *q, *k, *v, *ctx;
    cudaGetSymbolAddress((void**)&h,   g_h);
    cudaGetSymbolAddress((void**)&q,   g_q);
    cudaGetSymbolAddress((void**)&k,   g_k);
    cudaGetSymbolAddress((void**)&v,   g_v);
    cudaGetSymbolAddress((void**)&ctx, g_ctx);

    ln_kernel<<<MROWS, 256>>>(hs, gamma, beta, h);

    dim3 qkvgrid(HID / BN, MROWS / BM, 3);   // (8, 32, 3)
    sgemm_qkv<<<qkvgrid, 256>>>(h, Wq, Wk, Wv, bq, bk, bv, q, k, v,
                                MROWS, HID, HID);

    cudaFuncSetAttribute(attn_kernel, cudaFuncAttributeMaxDynamicSharedMemorySize,
                         ATTN_SMEM_BYTES);
    dim3 agrid(SEQ / QT, NH, BATCH);    // (16, 16, 2)
    attn_kernel<<<agrid, 256, ATTN_SMEM_BYTES>>>(q, k, v, amask, ctx);

    dim3 ggrid(HID / BN, MROWS / BM);   // (8, 32)
    sgemm_one<<<ggrid, 256>>>(ctx, Wd, bd, out, MROWS, HID, HID);
}

// round 17
// speedup vs baseline: 1.0428x; 1.0428x over previous
#include <cuda_runtime.h>
#include <cuda_bf16.h>
#include <cstdint>

// Problem constants
#define BATCH 2
#define SEQ   2048
#define HID   1024
#define NH    16
#define HD    64
#define MROWS (BATCH * SEQ)   // 4096

// ---------------- scratch (device globals; no allocation allowed) -------
__device__ float g_h[MROWS * HID];
__device__ float g_q[MROWS * HID];
__device__ float g_k[MROWS * HID];
__device__ float g_v[MROWS * HID];
__device__ float g_ctx[MROWS * HID];

// ---------------- helpers -----------------------------------------------
__device__ __forceinline__ uint32_t smem_u32(const void* p) {
    uint32_t a;
    asm("{ .reg .u64 t; cvta.to.shared.u64 t, %1; cvt.u32.u64 %0, t; }"
        : "=r"(a) : "l"(p));
    return a;
}
#define CP_ASYNC16(dst, src) \
    asm volatile("cp.async.cg.shared.global [%0], [%1], 16;" \
                 :: "r"(dst), "l"(src) : "memory")
#define CP_COMMIT() asm volatile("cp.async.commit_group;" ::: "memory")
#define CP_WAIT0()  asm volatile("cp.async.wait_group 0;" ::: "memory")

// ---------------- LayerNorm --------------------------------------------
__global__ void __launch_bounds__(256) ln_kernel(const float* __restrict__ X,
                                                 const float* __restrict__ gamma,
                                                 const float* __restrict__ beta,
                                                 float* __restrict__ Y) {
    int row = blockIdx.x;
    const float4* xr = (const float4*)(X + (size_t)row * HID);
    float4 v = xr[threadIdx.x];
    float s  = v.x + v.y + v.z + v.w;
    float ss = v.x*v.x + v.y*v.y + v.z*v.z + v.w*v.w;

    #pragma unroll
    for (int off = 16; off; off >>= 1) {
        s  += __shfl_xor_sync(0xffffffffu, s,  off);
        ss += __shfl_xor_sync(0xffffffffu, ss, off);
    }
    __shared__ float rs[8], rss[8];
    int w = threadIdx.x >> 5, ln = threadIdx.x & 31;
    if (ln == 0) { rs[w] = s; rss[w] = ss; }
    __syncthreads();
    float ts = 0.f, tss = 0.f;
    #pragma unroll
    for (int i = 0; i < 8; i++) { ts += rs[i]; tss += rss[i]; }
    float mu  = ts * (1.0f / HID);
    float var = tss * (1.0f / HID) - mu * mu;
    float inv = rsqrtf(var + 1e-12f);

    float4 g  = ((const float4*)gamma)[threadIdx.x];
    float4 be = ((const float4*)beta)[threadIdx.x];
    float4 r;
    r.x = (v.x - mu) * inv * g.x + be.x;
    r.y = (v.y - mu) * inv * g.y + be.y;
    r.z = (v.z - mu) * inv * g.z + be.z;
    r.w = (v.w - mu) * inv * g.w + be.w;
    ((float4*)(Y + (size_t)row * HID))[threadIdx.x] = r;
}

// ========== SGEMM core (BKG=16, smem + register double-buffered) ========
// C[m][n] = sum_k A[m][k]*B[n][k] + bias[n]
#define BM 128
#define BN 128
#define BKG 16
#define SPAD 132
#define TILE_F (BKG * SPAD)   // 2112 floats per operand tile

__device__ __forceinline__ void gemm_core(const float* __restrict__ A,
                                          const float* __restrict__ B,
                                          const float* __restrict__ bias,
                                          float* __restrict__ C,
                                          int M, int N, int K,
                                          float* sm, int m0, int n0) {
    int tid = threadIdx.x;
    int tx = tid & 15, ty = tid >> 4;

    const float* Ab = A + (size_t)m0 * K;
    const float* Bb = B + (size_t)n0 * K;

    float c[8][8];
    #pragma unroll
    for (int i = 0; i < 8; i++)
        #pragma unroll
        for (int j = 0; j < 8; j++) c[i][j] = 0.f;

    float4 ra[2], rb[2];
    #define G_LDG(k0) do { \
        _Pragma("unroll") \
        for (int i = 0; i < 2; i++) { \
            int id = tid + (i << 8); \
            int row = id >> 2, kq = (id & 3) << 2; \
            ra[i] = *(const float4*)&Ab[(size_t)row * K + (k0) + kq]; \
            rb[i] = *(const float4*)&Bb[(size_t)row * K + (k0) + kq]; \
        } } while (0)
    #define G_STS(buf) do { \
        float* As_ = sm + (buf) * 2 * TILE_F; \
        float* Bs_ = As_ + TILE_F; \
        _Pragma("unroll") \
        for (int i = 0; i < 2; i++) { \
            int id = tid + (i << 8); \
            int row = id >> 2, kq = (id & 3) << 2; \
            As_[(kq + 0) * SPAD + row] = ra[i].x; \
            As_[(kq + 1) * SPAD + row] = ra[i].y; \
            As_[(kq + 2) * SPAD + row] = ra[i].z; \
            As_[(kq + 3) * SPAD + row] = ra[i].w; \
            Bs_[(kq + 0) * SPAD + row] = rb[i].x; \
            Bs_[(kq + 1) * SPAD + row] = rb[i].y; \
            Bs_[(kq + 2) * SPAD + row] = rb[i].z; \
            Bs_[(kq + 3) * SPAD + row] = rb[i].w; \
        } } while (0)

    G_LDG(0);
    G_STS(0);
    __syncthreads();

    const int nst = K / BKG;
    for (int it = 0; it < nst; it++) {
        int buf = it & 1;
        bool more = (it + 1) < nst;
        if (more) G_LDG((it + 1) * BKG);

        const float* As = sm + buf * 2 * TILE_F;
        const float* Bs = As + TILE_F;

        // register double-buffered fragments: load k+1 while computing k
        float4 fa0[2], fa1[2], fb0[2], fb1[2];
        fa0[0] = *(const float4*)&As[ty * 8];
        fa1[0] = *(const float4*)&As[ty * 8 + 4];
        fb0[0] = *(const float4*)&Bs[tx * 4];
        fb1[0] = *(const float4*)&Bs[tx * 4 + 64];
        #pragma unroll
        for (int k = 0; k < BKG; k++) {
            int cur = k & 1, nxt = cur ^ 1;
            if (k + 1 < BKG) {
                fa0[nxt] = *(const float4*)&As[(k + 1) * SPAD + ty * 8];
                fa1[nxt] = *(const float4*)&As[(k + 1) * SPAD + ty * 8 + 4];
                fb0[nxt] = *(const float4*)&Bs[(k + 1) * SPAD + tx * 4];
                fb1[nxt] = *(const float4*)&Bs[(k + 1) * SPAD + tx * 4 + 64];
            }
            float4 a0 = fa0[cur], a1 = fa1[cur];
            float4 b0 = fb0[cur], b1 = fb1[cur];
            #define G_ROW(i, av) \
                c[i][0] += (av) * b0.x; c[i][1] += (av) * b0.y; \
                c[i][2] += (av) * b0.z; c[i][3] += (av) * b0.w; \
                c[i][4] += (av) * b1.x; c[i][5] += (av) * b1.y; \
                c[i][6] += (av) * b1.z; c[i][7] += (av) * b1.w;
            G_ROW(0, a0.x) G_ROW(1, a0.y) G_ROW(2, a0.z) G_ROW(3, a0.w)
            G_ROW(4, a1.x) G_ROW(5, a1.y) G_ROW(6, a1.z) G_ROW(7, a1.w)
            #undef G_ROW
        }
        if (more) {
            G_STS(buf ^ 1);
            __syncthreads();
        }
    }

    // epilogue: cols n0 + tx*4 (j 0-3) and n0 + 64 + tx*4 (j 4-7)
    float4 bi0 = *(const float4*)&bias[n0 + tx * 4];
    float4 bi1 = *(const float4*)&bias[n0 + 64 + tx * 4];
    #pragma unroll
    for (int i = 0; i < 8; i++) {
        int row = m0 + ty * 8 + i;
        float4 r0, r1;
        r0.x = c[i][0] + bi0.x; r0.y = c[i][1] + bi0.y;
        r0.z = c[i][2] + bi0.z; r0.w = c[i][3] + bi0.w;
        r1.x = c[i][4] + bi1.x; r1.y = c[i][5] + bi1.y;
        r1.z = c[i][6] + bi1.z; r1.w = c[i][7] + bi1.w;
        *(float4*)&C[(size_t)row * N + n0 + tx * 4]      = r0;
        *(float4*)&C[(size_t)row * N + n0 + 64 + tx * 4] = r1;
    }
    #undef G_LDG
    #undef G_STS
}

// Fused QKV: blockIdx.z selects (W, bias, C)
__global__ void __launch_bounds__(256, 2) sgemm_qkv(const float* __restrict__ A,
                                                    const float* __restrict__ W0,
                                                    const float* __restrict__ W1,
                                                    const float* __restrict__ W2,
                                                    const float* __restrict__ b0,
                                                    const float* __restrict__ b1,
                                                    const float* __restrict__ b2,
                                                    float* __restrict__ C0,
                                                    float* __restrict__ C1,
                                                    float* __restrict__ C2,
                                                    int M, int N, int K) {
    __shared__ float sm[4 * TILE_F];
    int z = blockIdx.z;
    const float* B    = (z == 0) ? W0 : (z == 1) ? W1 : W2;
    const float* bias = (z == 0) ? b0 : (z == 1) ? b1 : b2;
    float* C          = (z == 0) ? C0 : (z == 1) ? C1 : C2;
    gemm_core(A, B, bias, C, M, N, K, sm,
              blockIdx.y * BM, blockIdx.x * BN);
}

// Single GEMM (output projection)
__global__ void __launch_bounds__(256, 2) sgemm_one(const float* __restrict__ A,
                                                    const float* __restrict__ B,
                                                    const float* __restrict__ bias,
                                                    float* __restrict__ C,
                                                    int M, int N, int K) {
    __shared__ float sm[4 * TILE_F];
    gemm_core(A, B, bias, C, M, N, K, sm,
              blockIdx.y * BM, blockIdx.x * BN);
}

// ------- Flash attention: R15 (best-known) ------------------------------
// Max-free softmax (scores bounded; mask exp underflows to 0 cleanly).
#define QT 128
#define KT 64
#define QSTR 132
#define KSTR 68
#define PSTR 68    // floats per q-row of P (64 k + 4 pad); 17 float4s
// floats: Q 64*132 + K 64*68 + V 64*68 + P 128*68 + msk 64 = 25920 (103.7 KB)
#define ATTN_SMEM_FLOATS (HD * QSTR + 2 * KT * KSTR + QT * PSTR + KT)
#define ATTN_SMEM_BYTES (ATTN_SMEM_FLOATS * 4)

__global__ void __launch_bounds__(256, 2) attn_kernel(const float* __restrict__ Q,
                                                      const float* __restrict__ K,
                                                      const float* __restrict__ V,
                                                      const float* __restrict__ amask,
                                                      float* __restrict__ O) {
    extern __shared__ float sm[];
    float* Qst = sm;                      // [HD][QSTR]  (d-major)
    float* Ksm = Qst + HD * QSTR;         // [HD][KSTR]  (d-major)
    float* Vsm = Ksm + KT * KSTR;         // [KT][KSTR]  (s-major)
    float* Psm = Vsm + KT * KSTR;         // [QT][PSTR]  (q-major)
    float* msk = Psm + QT * PSTR;         // [KT]
    float4* P4 = (float4*)Psm;            // stride 17 float4 per q-row
    const float4* V4 = (const float4*)Vsm;  // stride 17 float4 per s-row
    uint32_t su = smem_u32(sm);
    const uint32_t v_off = (uint32_t)((HD * QSTR + KT * KSTR) * 4);

    int b = blockIdx.z, hh = blockIdx.y;
    int q0 = blockIdx.x * QT;
    int tid = threadIdx.x;
    int tx = tid & 15, ty = tid >> 4;
    int sld = tid >> 4;        // s-row for loading (0..15 per j-step)
    int d4  = (tid & 15) * 4;  // d-quad for loading

    size_t rowbase = ((size_t)b * SEQ) * HID + hh * HD;

    float4 kreg[4];
    float mreg = 1.0f;
    #define K_LDG(kk) do { \
        _Pragma("unroll") \
        for (int j = 0; j < 4; j++) { \
            int s = sld + j * 16; \
            kreg[j] = *(const float4*)&K[rowbase + (size_t)((kk) + s) * HID + d4]; \
        } \
        if (tid < KT) mreg = amask[b * SEQ + (kk) + tid]; \
        } while (0)
    #define K_STS() do { \
        _Pragma("unroll") \
        for (int j = 0; j < 4; j++) { \
            int s = sld + j * 16; \
            Ksm[(d4 + 0) * KSTR + s] = kreg[j].x; \
            Ksm[(d4 + 1) * KSTR + s] = kreg[j].y; \
            Ksm[(d4 + 2) * KSTR + s] = kreg[j].z; \
            Ksm[(d4 + 3) * KSTR + s] = kreg[j].w; \
        } \
        if (tid < KT) msk[tid] = -1000.0f * (1.0f - mreg); \
        } while (0)
    #define V_CPA(kk) do { \
        _Pragma("unroll") \
        for (int j = 0; j < 4; j++) { \
            int s = sld + j * 16; \
            uint32_t dst = su + v_off + (uint32_t)(s * KSTR + d4) * 4; \
            CP_ASYNC16(dst, &V[rowbase + (size_t)((kk) + s) * HID + d4]); \
        } } while (0)

    // prologue: V(0) async, Q tile (transposed), K(0)+mask via regs
    V_CPA(0);
    CP_COMMIT();
    for (int idx = tid; idx < QT * HD; idx += 256) {
        int s = idx >> 6, d = idx & 63;
        Qst[d * QSTR + s] = Q[rowbase + (size_t)(q0 + s) * HID + d];
    }
    K_LDG(0);
    K_STS();
    CP_WAIT0();
    __syncthreads();   // Q, K(0), msk(0), V(0) all visible

    float l_i[8], o[8][4];
    #pragma unroll
    for (int i = 0; i < 8; i++) {
        l_i[i] = 0.f;
        #pragma unroll
        for (int dd = 0; dd < 4; dd++) o[i][dd] = 0.f;
    }

    for (int kk = 0; kk < SEQ; kk += KT) {
        bool more = (kk + KT) < SEQ;
        if (more) K_LDG(kk + KT);   // lands during QK/softmax

        // S = Q K^T   (reads Qst, Ksm)
        float sreg[8][4];
        #pragma unroll
        for (int i = 0; i < 8; i++)
            #pragma unroll
            for (int j = 0; j < 4; j++) sreg[i][j] = 0.f;

        #pragma unroll 4
        for (int d = 0; d < HD; d++) {
            float4 a0 = *(float4*)&Qst[d * QSTR + ty * 8];
            float4 a1 = *(float4*)&Qst[d * QSTR + ty * 8 + 4];
            float4 bq = *(float4*)&Ksm[d * KSTR + tx * 4];
            #define A_SR(i, av) \
                sreg[i][0] += (av) * bq.x; sreg[i][1] += (av) * bq.y; \
                sreg[i][2] += (av) * bq.z; sreg[i][3] += (av) * bq.w;
            A_SR(0, a0.x) A_SR(1, a0.y) A_SR(2, a0.z) A_SR(3, a0.w)
            A_SR(4, a1.x) A_SR(5, a1.y) A_SR(6, a1.z) A_SR(7, a1.w)
            #undef A_SR
        }
        float mk[4];
        #pragma unroll
        for (int j = 0; j < 4; j++) mk[j] = msk[tx * 4 + j];

        // max-free softmax: p = exp(s/8 + mask); accumulate l; write P
        #pragma unroll
        for (int i = 0; i < 8; i++) {
            float lt = 0.f;
            #pragma unroll
            for (int j = 0; j < 4; j++) {
                float p = __expf(sreg[i][j] * 0.125f + mk[j]);
                sreg[i][j] = p;
                lt += p;
            }
            #pragma unroll
            for (int off = 8; off; off >>= 1)
                lt += __shfl_xor_sync(0xffffffffu, lt, off);
            l_i[i] += lt;
            float4 pv;
            pv.x = sreg[i][0]; pv.y = sreg[i][1];
            pv.z = sreg[i][2]; pv.w = sreg[i][3];
            P4[(ty * 8 + i) * 17 + tx] = pv;   // row q, col-quad tx (k=4tx..4tx+3)
        }
        CP_WAIT0();        // V(kk) landed (issuing thread)
        __syncthreads();   // (A) P + V(kk) visible; K(kk)/msk readers done

        if (more) K_STS();   // store K(kk+1)+msk — K readers finished at (A)

        // O += P @ V : kr blocked by 4; per-accumulator kr order = 0..63 asc
        #pragma unroll 4
        for (int kr4 = 0; kr4 < KT / 4; kr4++) {
            float4 vv0 = V4[(4 * kr4 + 0) * 17 + tx];
            float4 vv1 = V4[(4 * kr4 + 1) * 17 + tx];
            float4 vv2 = V4[(4 * kr4 + 2) * 17 + tx];
            float4 vv3 = V4[(4 * kr4 + 3) * 17 + tx];
            #pragma unroll
            for (int ih = 0; ih < 8; ih += 4) {
                float4 pq0 = P4[(ty * 8 + ih + 0) * 17 + kr4];
                float4 pq1 = P4[(ty * 8 + ih + 1) * 17 + kr4];
                float4 pq2 = P4[(ty * 8 + ih + 2) * 17 + kr4];
                float4 pq3 = P4[(ty * 8 + ih + 3) * 17 + kr4];
                #define A_OV4(i, pq) \
                    o[i][0] += pq.x * vv0.x; o[i][1] += pq.x * vv0.y; \
                    o[i][2] += pq.x * vv0.z; o[i][3] += pq.x * vv0.w; \
                    o[i][0] += pq.y * vv1.x; o[i][1] += pq.y * vv1.y; \
                    o[i][2] += pq.y * vv1.z; o[i][3] += pq.y * vv1.w; \
                    o[i][0] += pq.z * vv2.x; o[i][1] += pq.z * vv2.y; \
                    o[i][2] += pq.z * vv2.z; o[i][3] += pq.z * vv2.w; \
                    o[i][0] += pq.w * vv3.x; o[i][1] += pq.w * vv3.y; \
                    o[i][2] += pq.w * vv3.z; o[i][3] += pq.w * vv3.w;
                A_OV4(ih + 0, pq0)
                A_OV4(ih + 1, pq1)
                A_OV4(ih + 2, pq2)
                A_OV4(ih + 3, pq3)
                #undef A_OV4
            }
        }
        __syncthreads();   // (B) PV done: V free, P free, K(kk+1) visible
        if (more) {
            V_CPA(kk + KT);
            CP_COMMIT();
        }
    }

    #pragma unroll
    for (int i = 0; i < 8; i++) {
        float inv = 1.0f / l_i[i];
        int s = q0 + ty * 8 + i;
        float4 r;
        r.x = o[i][0] * inv; r.y = o[i][1] * inv;
        r.z = o[i][2] * inv; r.w = o[i][3] * inv;
        *(float4*)&O[rowbase + (size_t)s * HID + tx * 4] = r;
    }
    #undef K_LDG
    #undef K_STS
    #undef V_CPA
}

// ---------------- launch -------------------------------------------------
extern "C" void kernel_launch(void* const* d_in, const int* in_sizes, int n_in,
                              void* d_out, int out_size) {
    const float* hs    = (const float*)d_in[0];
    const float* amask = (const float*)d_in[1];
    const float* Wq    = (const float*)d_in[2];
    const float* bq    = (const float*)d_in[3];
    const float* Wk    = (const float*)d_in[4];
    const float* bk    = (const float*)d_in[5];
    const float* Wv    = (const float*)d_in[6];
    const float* bv    = (const float*)d_in[7];
    const float* Wd    = (const float*)d_in[8];
    const float* bd    = (const float*)d_in[9];
    const float* gamma = (const float*)d_in[10];
    const float* beta  = (const float*)d_in[11];
    float* out = (float*)d_out;

    float *h, *q, *k, *v, *ctx;
    cudaGetSymbolAddress((void**)&h,   g_h);
    cudaGetSymbolAddress((void**)&q,   g_q);
    cudaGetSymbolAddress((void**)&k,   g_k);
    cudaGetSymbolAddress((void**)&v,   g_v);
    cudaGetSymbolAddress((void**)&ctx, g_ctx);

    ln_kernel<<<MROWS, 256>>>(hs, gamma, beta, h);

    dim3 qkvgrid(HID / BN, MROWS / BM, 3);   // (8, 32, 3)
    sgemm_qkv<<<qkvgrid, 256>>>(h, Wq, Wk, Wv, bq, bk, bv, q, k, v,
                                MROWS, HID, HID);

    cudaFuncSetAttribute(attn_kernel, cudaFuncAttributeMaxDynamicSharedMemorySize,
                         ATTN_SMEM_BYTES);
    dim3 agrid(SEQ / QT, NH, BATCH);    // (16, 16, 2)
    attn_kernel<<<agrid, 256, ATTN_SMEM_BYTES>>>(q, k, v, amask, ctx);

    dim3 ggrid(HID / BN, MROWS / BM);   // (8, 32)
    sgemm_one<<<ggrid, 256>>>(ctx, Wd, bd, out, MROWS, HID, HID);
}